// round 15
// baseline (speedup 1.0000x reference)
#include <cuda_runtime.h>

#define DIM   256
#define BATCH 256
#define MCn   128
#define MPn   256
#define NMAX  20000

// XOR swizzle: float4-column c4 of row r stored at physical c4 ^ (r & 7)
#define SWZ(r, c4) ((c4) ^ ((r) & 7))

// ---------------- static device scratch ----------------
__device__ float g_cq[NMAX*DIM];
__device__ float g_ck[NMAX*DIM];
__device__ float g_cv[NMAX*DIM];
__device__ float g_pq[NMAX*DIM];
__device__ float g_pk[NMAX*DIM];
__device__ float g_pv[NMAX*DIM];
__device__ float g_cf[BATCH*MCn*DIM];   // comp_fused (pre-gate)
__device__ float g_pf[BATCH*MPn*DIM];   // prot_fused (pre-gate)
__device__ float g_gc[BATCH*MCn*DIM];   // gated comp_fused
__device__ float g_gp[BATCH*MPn*DIM];   // gated prot_fused
__device__ float g_impc[BATCH*MCn];
__device__ float g_impp[BATCH*MPn];

__global__ void init_impp_k() {
    int i = blockIdx.x * blockDim.x + threadIdx.x;
    if (i < BATCH*MPn) g_impp[i] = 0.0f;
}

// ---------------- projection GEMM: 3 outputs per launch ----------------
__global__ void __launch_bounds__(256, 3)
gemm3(const float* __restrict__ X,
      const float* __restrict__ W0, const float* __restrict__ bz0, float* __restrict__ O0,
      const float* __restrict__ W1, const float* __restrict__ bz1, float* __restrict__ O1,
      const float* __restrict__ W2, const float* __restrict__ bz2, float* __restrict__ O2,
      int M)
{
    __shared__ float sX[2][16][132];
    __shared__ float sW[2][16][68];
    const float* W; const float* bias; float* Out;
    if (blockIdx.z == 0)      { W = W0; bias = bz0; Out = O0; }
    else if (blockIdx.z == 1) { W = W1; bias = bz1; Out = O1; }
    else                      { W = W2; bias = bz2; Out = O2; }
    const int tid = threadIdx.x;
    const int bm = blockIdx.y * 128;
    const int bn = blockIdx.x * 64;
    const int ty = tid >> 4, tx = tid & 15;
    const int xr = tid >> 1, xk = (tid & 1) * 8;
    const int wr = tid & 63, wk = (tid >> 6) * 4;
    const float* xp = X + (size_t)(bm + xr) * 256 + xk;
    const float* wp = W + (size_t)(bn + wr) * 256 + wk;
    const bool xv = (bm + xr) < M;

    float4 rx0 = xv ? *(const float4*)xp       : make_float4(0.f,0.f,0.f,0.f);
    float4 rx1 = xv ? *(const float4*)(xp + 4) : make_float4(0.f,0.f,0.f,0.f);
    float4 rw0 = *(const float4*)wp;
    sX[0][xk+0][xr]=rx0.x; sX[0][xk+1][xr]=rx0.y; sX[0][xk+2][xr]=rx0.z; sX[0][xk+3][xr]=rx0.w;
    sX[0][xk+4][xr]=rx1.x; sX[0][xk+5][xr]=rx1.y; sX[0][xk+6][xr]=rx1.z; sX[0][xk+7][xr]=rx1.w;
    sW[0][wk+0][wr]=rw0.x; sW[0][wk+1][wr]=rw0.y; sW[0][wk+2][wr]=rw0.z; sW[0][wk+3][wr]=rw0.w;
    __syncthreads();

    float acc[8][4] = {};
#pragma unroll 1
    for (int s = 0; s < 16; s++) {
        const int cur = s & 1;
        if (s < 15) {
            const float* xq = xp + (s+1)*16;
            rx0 = xv ? *(const float4*)xq       : make_float4(0.f,0.f,0.f,0.f);
            rx1 = xv ? *(const float4*)(xq + 4) : make_float4(0.f,0.f,0.f,0.f);
            rw0 = *(const float4*)(wp + (s+1)*16);
        }
#pragma unroll
        for (int k = 0; k < 16; k++) {
            float4 a0 = *(const float4*)&sX[cur][k][ty*8];
            float4 a1 = *(const float4*)&sX[cur][k][ty*8+4];
            float4 bq = *(const float4*)&sW[cur][k][tx*4];
            float av[8] = {a0.x,a0.y,a0.z,a0.w,a1.x,a1.y,a1.z,a1.w};
            float bv[4] = {bq.x,bq.y,bq.z,bq.w};
#pragma unroll
            for (int i = 0; i < 8; i++)
#pragma unroll
                for (int j = 0; j < 4; j++) acc[i][j] += av[i]*bv[j];
        }
        if (s < 15) {
            const int nxt = cur ^ 1;
            sX[nxt][xk+0][xr]=rx0.x; sX[nxt][xk+1][xr]=rx0.y; sX[nxt][xk+2][xr]=rx0.z; sX[nxt][xk+3][xr]=rx0.w;
            sX[nxt][xk+4][xr]=rx1.x; sX[nxt][xk+5][xr]=rx1.y; sX[nxt][xk+6][xr]=rx1.z; sX[nxt][xk+7][xr]=rx1.w;
            sW[nxt][wk+0][wr]=rw0.x; sW[nxt][wk+1][wr]=rw0.y; sW[nxt][wk+2][wr]=rw0.z; sW[nxt][wk+3][wr]=rw0.w;
            __syncthreads();
        }
    }
    float4 bb = *(const float4*)(bias + bn + tx*4);
    float bvv[4] = {bb.x, bb.y, bb.z, bb.w};
#pragma unroll
    for (int i = 0; i < 8; i++) {
        int r = bm + ty*8 + i;
        if (r < M)
            *(float4*)(Out + (size_t)r*256 + bn + tx*4) =
                make_float4(acc[i][0]+bvv[0], acc[i][1]+bvv[1],
                            acc[i][2]+bvv[2], acc[i][3]+bvv[3]);
    }
}

// ---------------- gated GEMM: Out = X * sigmoid(X@W^T + b), length-skipped ----------------
template<int SEQ>
__global__ void __launch_bounds__(256, 3)
gemmg(const float* __restrict__ X, const float* __restrict__ W,
      const float* __restrict__ bias, float* __restrict__ Out,
      const int* __restrict__ lens)
{
    __shared__ float sX[2][16][132];
    __shared__ float sW[2][16][68];
    const int tid = threadIdx.x;
    const int bm = blockIdx.y * 128;
    const int bn = blockIdx.x * 64;
    const int b = bm / SEQ;
    const int lenloc = lens[b] - (bm - b*SEQ);
    if (lenloc <= 0) return;
    const bool wvalid = ((tid >> 5) * 16) < lenloc;
    const int ty = tid >> 4, tx = tid & 15;
    const int xr = tid >> 1, xk = (tid & 1) * 8;
    const int wr = tid & 63, wk = (tid >> 6) * 4;
    const float* xp = X + (size_t)(bm + xr) * 256 + xk;
    const float* wp = W + (size_t)(bn + wr) * 256 + wk;

    float4 rx0 = *(const float4*)xp;
    float4 rx1 = *(const float4*)(xp + 4);
    float4 rw0 = *(const float4*)wp;
    sX[0][xk+0][xr]=rx0.x; sX[0][xk+1][xr]=rx0.y; sX[0][xk+2][xr]=rx0.z; sX[0][xk+3][xr]=rx0.w;
    sX[0][xk+4][xr]=rx1.x; sX[0][xk+5][xr]=rx1.y; sX[0][xk+6][xr]=rx1.z; sX[0][xk+7][xr]=rx1.w;
    sW[0][wk+0][wr]=rw0.x; sW[0][wk+1][wr]=rw0.y; sW[0][wk+2][wr]=rw0.z; sW[0][wk+3][wr]=rw0.w;
    __syncthreads();

    float acc[8][4] = {};
#pragma unroll 1
    for (int s = 0; s < 16; s++) {
        const int cur = s & 1;
        if (s < 15) {
            const float* xq = xp + (s+1)*16;
            rx0 = *(const float4*)xq;
            rx1 = *(const float4*)(xq + 4);
            rw0 = *(const float4*)(wp + (s+1)*16);
        }
        if (wvalid) {
#pragma unroll
            for (int k = 0; k < 16; k++) {
                float4 a0 = *(const float4*)&sX[cur][k][ty*8];
                float4 a1 = *(const float4*)&sX[cur][k][ty*8+4];
                float4 bq = *(const float4*)&sW[cur][k][tx*4];
                float av[8] = {a0.x,a0.y,a0.z,a0.w,a1.x,a1.y,a1.z,a1.w};
                float bv[4] = {bq.x,bq.y,bq.z,bq.w};
#pragma unroll
                for (int i = 0; i < 8; i++)
#pragma unroll
                    for (int j = 0; j < 4; j++) acc[i][j] += av[i]*bv[j];
            }
        }
        if (s < 15) {
            const int nxt = cur ^ 1;
            sX[nxt][xk+0][xr]=rx0.x; sX[nxt][xk+1][xr]=rx0.y; sX[nxt][xk+2][xr]=rx0.z; sX[nxt][xk+3][xr]=rx0.w;
            sX[nxt][xk+4][xr]=rx1.x; sX[nxt][xk+5][xr]=rx1.y; sX[nxt][xk+6][xr]=rx1.z; sX[nxt][xk+7][xr]=rx1.w;
            sW[nxt][wk+0][wr]=rw0.x; sW[nxt][wk+1][wr]=rw0.y; sW[nxt][wk+2][wr]=rw0.z; sW[nxt][wk+3][wr]=rw0.w;
            __syncthreads();
        }
    }
    if (!wvalid) return;
    float4 bb = *(const float4*)(bias + bn + tx*4);
    float bvv[4] = {bb.x, bb.y, bb.z, bb.w};
#pragma unroll
    for (int i = 0; i < 8; i++) {
        int r = bm + ty*8 + i;
        float4 xr4 = *(const float4*)(X + (size_t)r*256 + bn + tx*4);
        float xa[4] = {xr4.x, xr4.y, xr4.z, xr4.w};
        float o[4];
#pragma unroll
        for (int j = 0; j < 4; j++) {
            float logit = acc[i][j] + bvv[j];
            o[j] = xa[j] * (1.0f / (1.0f + __expf(-logit)));
        }
        *(float4*)(Out + (size_t)r*256 + bn + tx*4) = make_float4(o[0],o[1],o[2],o[3]);
    }
}

// ---------------- compound->protein attention (512 threads, swizzled K/V tile) ----------------
// smem: q[32][260], s[32][256], kt[128][256] XOR-swizzled
__global__ void __launch_bounds__(512)
att_cp(const int* __restrict__ comp_idx, const int* __restrict__ prot_idx,
       const int* __restrict__ comp_lens, const int* __restrict__ prot_lens)
{
    extern __shared__ float smem[];
    float* q  = smem;                   // 32*260
    float* s  = smem + 32*260;          // 32*256
    float* kt = smem + 32*260 + 32*256; // 128*256 swizzled
    float4* kt4 = (float4*)kt;
    const int b = blockIdx.y;
    const int r0 = blockIdx.x * 32;
    const int tid = threadIdx.x, lane = tid & 31, w = tid >> 5;
    const int clen = comp_lens[b], plen = prot_lens[b];
    if (r0 >= clen) return;
    const int lsw = lane & 7;

    // gather q rows (scaled by 1/16)
    for (int i = tid; i < 32*64; i += 512) {
        int row = i >> 6, kq = (i & 63) << 2;
        int gi = comp_idx[b*MCn + r0 + row];
        float4 v = *(const float4*)(g_cq + (size_t)gi*256 + kq);
        v.x *= 0.0625f; v.y *= 0.0625f; v.z *= 0.0625f; v.w *= 0.0625f;
        *(float4*)&q[row*260 + kq] = v;
    }
    __syncthreads();

    // scores in 128-col chunks
    for (int m0 = 0; m0 < plen; m0 += 128) {
        int mrows = plen - m0; if (mrows > 128) mrows = 128;
        int mr4 = (mrows + 3) & ~3;
        for (int i = tid; i < 128*64; i += 512) {
            int row = i >> 6;
            if (row < mr4) {
                int c4 = i & 63;
                int gi = prot_idx[b*MPn + m0 + row];
                kt4[row*64 + SWZ(row, c4)] = *(const float4*)(g_pk + (size_t)gi*256 + c4*4);
            }
        }
        __syncthreads();
        float acc[2][4] = {};
#pragma unroll 2
        for (int kc = 0; kc < 64; kc++) {
            float4 qv[2];
#pragma unroll
            for (int i = 0; i < 2; i++) qv[i] = *(const float4*)&q[(2*w+i)*260 + kc*4];
            const int swc = kc ^ lsw;
#pragma unroll
            for (int j = 0; j < 4; j++) {
                if (32*j < mrows) {
                    float4 kv = kt4[(lane + 32*j)*64 + swc];
#pragma unroll
                    for (int i = 0; i < 2; i++)
                        acc[i][j] += qv[i].x*kv.x + qv[i].y*kv.y + qv[i].z*kv.z + qv[i].w*kv.w;
                }
            }
        }
#pragma unroll
        for (int i = 0; i < 2; i++)
#pragma unroll
            for (int j = 0; j < 4; j++)
                s[(2*w+i)*256 + m0 + lane + 32*j] = acc[i][j];
        __syncthreads();
    }

    // masked softmax per row + imp_c (warp w owns rows 2w, 2w+1)
#pragma unroll
    for (int i = 0; i < 2; i++) {
        int r = 2*w + i;
        bool rvalid = (r0 + r) < clen;
        float v[8];
        float mx = -3.4e38f;
#pragma unroll
        for (int jj = 0; jj < 8; jj++) {
            int m = lane + 32*jj;
            float sc = s[r*256 + m];
            if (!rvalid || m >= plen) sc = -1e9f;
            v[jj] = sc; mx = fmaxf(mx, sc);
        }
#pragma unroll
        for (int o = 16; o; o >>= 1) mx = fmaxf(mx, __shfl_xor_sync(0xffffffffu, mx, o));
        float sum = 0.f;
#pragma unroll
        for (int jj = 0; jj < 8; jj++) { v[jj] = __expf(v[jj] - mx); sum += v[jj]; }
#pragma unroll
        for (int o = 16; o; o >>= 1) sum += __shfl_xor_sync(0xffffffffu, sum, o);
        float inv = 1.0f / sum;
        float pmax = 0.f;
#pragma unroll
        for (int jj = 0; jj < 8; jj++) {
            float p = v[jj] * inv;
            s[r*256 + lane + 32*jj] = p;
            pmax = fmaxf(pmax, p);
        }
#pragma unroll
        for (int o = 16; o; o >>= 1) pmax = fmaxf(pmax, __shfl_xor_sync(0xffffffffu, pmax, o));
        if (lane == 0) g_impc[b*MCn + r0 + r] = pmax;
    }
    __syncthreads();

    // imp_p column max over valid rows
    if (tid < 256) {
        int nval = clen - r0; if (nval > 32) nval = 32;
        float vmax = 0.f;
        for (int r = 0; r < nval; r++) vmax = fmaxf(vmax, s[r*256 + tid]);
        atomicMax((int*)&g_impp[b*MPn + tid], __float_as_int(vmax));
    }

    // PV in 128-col chunks (V tile swizzled same way)
    float accO[2][8] = {};
    for (int c0 = 0; c0 < plen; c0 += 128) {
        int crows = plen - c0; if (crows > 128) crows = 128;
        int cr4 = (crows + 3) & ~3;
        __syncthreads();
        for (int i = tid; i < 128*64; i += 512) {
            int row = i >> 6;
            if (row < cr4) {
                int c4 = i & 63;
                int gi = prot_idx[b*MPn + c0 + row];
                kt4[row*64 + SWZ(row, c4)] = *(const float4*)(g_pv + (size_t)gi*256 + c4*4);
            }
        }
        __syncthreads();
#pragma unroll 2
        for (int c = 0; c < cr4; c += 4) {
            float pr[2][4];
#pragma unroll
            for (int i = 0; i < 2; i++) {
                float4 p = *(const float4*)&s[(2*w+i)*256 + c0 + c];
                pr[i][0]=p.x; pr[i][1]=p.y; pr[i][2]=p.z; pr[i][3]=p.w;
            }
#pragma unroll
            for (int cc = 0; cc < 4; cc++) {
                const int row = c + cc;
                const int rs = row & 7;
                float4 v0 = kt4[row*64 + (lane ^ rs)];
                float4 v1 = kt4[row*64 + ((32 + lane) ^ rs)];
#pragma unroll
                for (int i = 0; i < 2; i++) {
                    float p = pr[i][cc];
                    accO[i][0] += p*v0.x; accO[i][1] += p*v0.y;
                    accO[i][2] += p*v0.z; accO[i][3] += p*v0.w;
                    accO[i][4] += p*v1.x; accO[i][5] += p*v1.y;
                    accO[i][6] += p*v1.z; accO[i][7] += p*v1.w;
                }
            }
        }
    }
#pragma unroll
    for (int i = 0; i < 2; i++) {
        size_t base = (size_t)(b*MCn + r0 + 2*w + i)*256;
        *(float4*)(g_cf + base + lane*4)       = make_float4(accO[i][0],accO[i][1],accO[i][2],accO[i][3]);
        *(float4*)(g_cf + base + 128 + lane*4) = make_float4(accO[i][4],accO[i][5],accO[i][6],accO[i][7]);
    }
}

// ---------------- protein->compound attention (512 threads, swizzled K/V tile) ----------------
// smem: q[32][260], s[32][128], kt[128][256] swizzled
__global__ void __launch_bounds__(512)
att_pc(const int* __restrict__ comp_idx, const int* __restrict__ prot_idx,
       const int* __restrict__ comp_lens, const int* __restrict__ prot_lens)
{
    extern __shared__ float smem[];
    float* q  = smem;                   // 32*260
    float* s  = smem + 32*260;          // 32*128
    float* kt = smem + 32*260 + 32*128; // 128*256 swizzled
    float4* kt4 = (float4*)kt;
    const int b = blockIdx.y;
    const int r0 = blockIdx.x * 32;
    const int tid = threadIdx.x, lane = tid & 31, w = tid >> 5;
    const int clen = comp_lens[b], plen = prot_lens[b];
    if (r0 >= plen) return;
    const int cr4 = (clen + 3) & ~3;
    const int lsw = lane & 7;

    for (int i = tid; i < 32*64; i += 512) {
        int row = i >> 6, kq = (i & 63) << 2;
        int gi = prot_idx[b*MPn + r0 + row];
        float4 v = *(const float4*)(g_pq + (size_t)gi*256 + kq);
        v.x *= 0.0625f; v.y *= 0.0625f; v.z *= 0.0625f; v.w *= 0.0625f;
        *(float4*)&q[row*260 + kq] = v;
    }
    // K tile (compound rows), swizzled
    for (int i = tid; i < 128*64; i += 512) {
        int row = i >> 6;
        if (row < cr4) {
            int c4 = i & 63;
            int gi = comp_idx[b*MCn + row];
            kt4[row*64 + SWZ(row, c4)] = *(const float4*)(g_ck + (size_t)gi*256 + c4*4);
        }
    }
    __syncthreads();

    {
        float acc[2][4] = {};
#pragma unroll 2
        for (int kc = 0; kc < 64; kc++) {
            float4 qv[2];
#pragma unroll
            for (int i = 0; i < 2; i++) qv[i] = *(const float4*)&q[(2*w+i)*260 + kc*4];
            const int swc = kc ^ lsw;
#pragma unroll
            for (int j = 0; j < 4; j++) {
                if (32*j < clen) {
                    float4 kv = kt4[(lane + 32*j)*64 + swc];
#pragma unroll
                    for (int i = 0; i < 2; i++)
                        acc[i][j] += qv[i].x*kv.x + qv[i].y*kv.y + qv[i].z*kv.z + qv[i].w*kv.w;
                }
            }
        }
#pragma unroll
        for (int i = 0; i < 2; i++)
#pragma unroll
            for (int j = 0; j < 4; j++)
                s[(2*w+i)*128 + lane + 32*j] = acc[i][j];
    }

    // masked softmax over 128 compound cols (warp-private rows)
#pragma unroll
    for (int i = 0; i < 2; i++) {
        int r = 2*w + i;
        bool rvalid = (r0 + r) < plen;
        float v[4];
        float mx = -3.4e38f;
#pragma unroll
        for (int jj = 0; jj < 4; jj++) {
            int n = lane + 32*jj;
            float sc = s[r*128 + n];
            if (!rvalid || n >= clen) sc = -1e9f;
            v[jj] = sc; mx = fmaxf(mx, sc);
        }
#pragma unroll
        for (int o = 16; o; o >>= 1) mx = fmaxf(mx, __shfl_xor_sync(0xffffffffu, mx, o));
        float sum = 0.f;
#pragma unroll
        for (int jj = 0; jj < 4; jj++) { v[jj] = __expf(v[jj] - mx); sum += v[jj]; }
#pragma unroll
        for (int o = 16; o; o >>= 1) sum += __shfl_xor_sync(0xffffffffu, sum, o);
        float inv = 1.0f / sum;
#pragma unroll
        for (int jj = 0; jj < 4; jj++)
            s[r*128 + lane + 32*jj] = v[jj] * inv;
    }
    __syncthreads();

    // V tile (compound rows from g_cv), swizzled, reuses kt
    for (int i = tid; i < 128*64; i += 512) {
        int row = i >> 6;
        if (row < cr4) {
            int c4 = i & 63;
            int gi = comp_idx[b*MCn + row];
            kt4[row*64 + SWZ(row, c4)] = *(const float4*)(g_cv + (size_t)gi*256 + c4*4);
        }
    }
    __syncthreads();

    float accO[2][8] = {};
#pragma unroll 2
    for (int c = 0; c < cr4; c += 4) {
        float pr[2][4];
#pragma unroll
        for (int i = 0; i < 2; i++) {
            float4 p = *(const float4*)&s[(2*w+i)*128 + c];
            pr[i][0]=p.x; pr[i][1]=p.y; pr[i][2]=p.z; pr[i][3]=p.w;
        }
#pragma unroll
        for (int cc = 0; cc < 4; cc++) {
            const int row = c + cc;
            const int rs = row & 7;
            float4 v0 = kt4[row*64 + (lane ^ rs)];
            float4 v1 = kt4[row*64 + ((32 + lane) ^ rs)];
#pragma unroll
            for (int i = 0; i < 2; i++) {
                float p = pr[i][cc];
                accO[i][0] += p*v0.x; accO[i][1] += p*v0.y;
                accO[i][2] += p*v0.z; accO[i][3] += p*v0.w;
                accO[i][4] += p*v1.x; accO[i][5] += p*v1.y;
                accO[i][6] += p*v1.z; accO[i][7] += p*v1.w;
            }
        }
    }
#pragma unroll
    for (int i = 0; i < 2; i++) {
        size_t base = (size_t)(b*MPn + r0 + 2*w + i)*256;
        *(float4*)(g_pf + base + lane*4)       = make_float4(accO[i][0],accO[i][1],accO[i][2],accO[i][3]);
        *(float4*)(g_pf + base + 128 + lane*4) = make_float4(accO[i][4],accO[i][5],accO[i][6],accO[i][7]);
    }
}

// ---------------- block reductions ----------------
__device__ __forceinline__ float blkMax(float v, float* red) {
#pragma unroll
    for (int o = 16; o; o >>= 1) v = fmaxf(v, __shfl_xor_sync(0xffffffffu, v, o));
    int w = threadIdx.x >> 5, l = threadIdx.x & 31;
    if (l == 0) red[w] = v;
    __syncthreads();
    if (threadIdx.x < 8) {
        float x = red[threadIdx.x];
#pragma unroll
        for (int o = 4; o; o >>= 1) x = fmaxf(x, __shfl_xor_sync(0x000000ffu, x, o));
        if (threadIdx.x == 0) red[0] = x;
    }
    __syncthreads();
    float r = red[0];
    __syncthreads();
    return r;
}

__device__ __forceinline__ float blkSum(float v, float* red) {
#pragma unroll
    for (int o = 16; o; o >>= 1) v += __shfl_xor_sync(0xffffffffu, v, o);
    int w = threadIdx.x >> 5, l = threadIdx.x & 31;
    if (l == 0) red[w] = v;
    __syncthreads();
    if (threadIdx.x < 8) {
        float x = red[threadIdx.x];
#pragma unroll
        for (int o = 4; o; o >>= 1) x += __shfl_xor_sync(0x000000ffu, x, o);
        if (threadIdx.x == 0) red[0] = x;
    }
    __syncthreads();
    float r = red[0];
    __syncthreads();
    return r;
}

// ---------------- finalize ----------------
__global__ void __launch_bounds__(256)
finalize_k(const int* __restrict__ comp_lens, const int* __restrict__ prot_lens,
           float* __restrict__ out)
{
    __shared__ float wc[128];
    __shared__ float wp[256];
    __shared__ float red[32];
    const int b = blockIdx.x, t = threadIdx.x;
    const int clen = comp_lens[b], plen = prot_lens[b];

    float x = -1e30f;
    if (t < 128 && t < clen) x = g_impc[b*MCn + t];
    float mx = blkMax(x, red);
    float e = (t < 128) ? __expf(x - mx) : 0.f;
    float sm = blkSum(e, red);
    if (t < 128) wc[t] = e / sm;

    float x2 = (t < plen) ? g_impp[b*MPn + t] : -1e30f;
    float mx2 = blkMax(x2, red);
    float e2 = __expf(x2 - mx2);
    float sm2 = blkSum(e2, red);
    wp[t] = e2 / sm2;
    __syncthreads();

    float h = 0.f;
    for (int n = 0; n < clen; n++)
        h += wc[n] * g_gc[(b*MCn + n)*256 + t];
    float dd = 0.f;
    for (int m = 0; m < plen; m++)
        dd += wp[m] * g_gp[(b*MPn + m)*256 + t];
    float logit = blkSum(h * dd, red);
    if (t == 0) out[b] = 1.0f / (1.0f + __expf(-logit));
}

// ---------------- host launch ----------------
extern "C" void kernel_launch(void* const* d_in, const int* in_sizes, int n_in,
                              void* d_out, int out_size)
{
    const float* comp_emb = (const float*)d_in[0];
    const float* prot_emb = (const float*)d_in[1];
    const float* Wq_c = (const float*)d_in[2];  const float* bq_c = (const float*)d_in[3];
    const float* Wk_c = (const float*)d_in[4];  const float* bk_c = (const float*)d_in[5];
    const float* Wv_c = (const float*)d_in[6];  const float* bv_c = (const float*)d_in[7];
    const float* Wq_p = (const float*)d_in[8];  const float* bq_p = (const float*)d_in[9];
    const float* Wk_p = (const float*)d_in[10]; const float* bk_p = (const float*)d_in[11];
    const float* Wv_p = (const float*)d_in[12]; const float* bv_p = (const float*)d_in[13];
    const float* Wg_c = (const float*)d_in[14]; const float* bg_c = (const float*)d_in[15];
    const float* Wg_p = (const float*)d_in[16]; const float* bg_p = (const float*)d_in[17];
    const int* comp_idx  = (const int*)d_in[18];
    const int* prot_idx  = (const int*)d_in[19];
    const int* comp_lens = (const int*)d_in[20];
    const int* prot_lens = (const int*)d_in[21];
    float* out = (float*)d_out;

    const int NC = in_sizes[0] / 256;
    const int NP = in_sizes[1] / 256;

    float *p_cq, *p_ck, *p_cv, *p_pq, *p_pk, *p_pv, *p_cf, *p_pf, *p_gc, *p_gp;
    cudaGetSymbolAddress((void**)&p_cq, g_cq);
    cudaGetSymbolAddress((void**)&p_ck, g_ck);
    cudaGetSymbolAddress((void**)&p_cv, g_cv);
    cudaGetSymbolAddress((void**)&p_pq, g_pq);
    cudaGetSymbolAddress((void**)&p_pk, g_pk);
    cudaGetSymbolAddress((void**)&p_pv, g_pv);
    cudaGetSymbolAddress((void**)&p_cf, g_cf);
    cudaGetSymbolAddress((void**)&p_pf, g_pf);
    cudaGetSymbolAddress((void**)&p_gc, g_gc);
    cudaGetSymbolAddress((void**)&p_gp, g_gp);

    const int SMEM_CP = (32*260 + 32*256 + 128*256) * 4;   // 197120
    const int SMEM_PC = (32*260 + 32*128 + 128*256) * 4;   // 180736
    cudaFuncSetAttribute(att_cp, cudaFuncAttributeMaxDynamicSharedMemorySize, SMEM_CP);
    cudaFuncSetAttribute(att_pc, cudaFuncAttributeMaxDynamicSharedMemorySize, SMEM_PC);

    init_impp_k<<<64, 1024>>>();

    gemm3<<<dim3(4, (NC + 127) / 128, 3), 256>>>(comp_emb,
        Wq_c, bq_c, p_cq,  Wk_c, bk_c, p_ck,  Wv_c, bv_c, p_cv, NC);
    gemm3<<<dim3(4, (NP + 127) / 128, 3), 256>>>(prot_emb,
        Wq_p, bq_p, p_pq,  Wk_p, bk_p, p_pk,  Wv_p, bv_p, p_pv, NP);

    att_cp<<<dim3(4, BATCH), 512, SMEM_CP>>>(comp_idx, prot_idx, comp_lens, prot_lens);
    att_pc<<<dim3(8, BATCH), 512, SMEM_PC>>>(comp_idx, prot_idx, comp_lens, prot_lens);

    gemmg<MCn><<<dim3(4, (BATCH*MCn)/128), 256>>>(p_cf, Wg_c, bg_c, p_gc, comp_lens);
    gemmg<MPn><<<dim3(4, (BATCH*MPn)/128), 256>>>(p_pf, Wg_p, bg_p, p_gp, prot_lens);

    finalize_k<<<BATCH, 256>>>(comp_lens, prot_lens, out);
}